// round 1
// baseline (speedup 1.0000x reference)
#include <cuda_runtime.h>

#define NB   8
#define CIN  256
#define TT   1024
#define HDS  8
#define DQK  64
#define DV   32
#define OCH  256

// Scratch (allocation-free rule: __device__ globals)
__device__ float g_q[NB * HDS * DQK * TT];   // [n][h][d][t]
__device__ float g_k[NB * HDS * DQK * TT];   // [n][h][d][t]
__device__ float g_v[NB * HDS * DV  * TT];   // [n][h][dv][t]
__device__ float g_ao[NB * OCH * TT];        // [n][c=h*32+dv][t]

// ---------------------------------------------------------------------------
// Kernel 1: fused QKV projection.
// y[n][o][t] = sum_c W[o][c] * x[n][c][t] + b[o],  o in [0,1280)
//   o <  512  -> q  (h=o/64,  d=o%64)        -> g_q[n][h][d][t]
//   o < 1024  -> k  (o'=o-512)               -> g_k[n][h][d][t]
//   else      -> v  (o'=o-1024, h=o'/32)     -> g_v[n][h][dv][t]
// grid: (T/64, 1280/64, NB), block: 256 (16x16, each thread 4x4, strided map)
// ---------------------------------------------------------------------------
__global__ __launch_bounds__(256) void qkv_kernel(
    const float* __restrict__ x, const float* __restrict__ Wq,
    const float* __restrict__ bq, const float* __restrict__ Wkv,
    const float* __restrict__ bkv)
{
    __shared__ float sW[64][33];
    __shared__ float sX[32][65];

    const int n  = blockIdx.z;
    const int o0 = blockIdx.y * 64;
    const int t0 = blockIdx.x * 64;
    const int tid = threadIdx.x;
    const int ty = tid >> 4, tx = tid & 15;

    const float* __restrict__ xb = x + (size_t)n * CIN * TT;

    float acc[4][4];
#pragma unroll
    for (int i = 0; i < 4; i++)
#pragma unroll
        for (int j = 0; j < 4; j++) acc[i][j] = 0.f;

    for (int k0 = 0; k0 < CIN; k0 += 32) {
        // W tile: 64 rows x 32 cols
#pragma unroll
        for (int i = 0; i < 8; i++) {
            int idx = tid + i * 256;
            int r = idx >> 5, c = idx & 31;
            int o = o0 + r;
            float w = (o < 512) ? Wq[(size_t)o * CIN + k0 + c]
                                : Wkv[(size_t)(o - 512) * CIN + k0 + c];
            sW[r][c] = w;
        }
        // X tile: 32 (c) x 64 (t)
#pragma unroll
        for (int i = 0; i < 8; i++) {
            int idx = tid + i * 256;
            int r = idx >> 6, c = idx & 63;
            sX[r][c] = xb[(size_t)(k0 + r) * TT + t0 + c];
        }
        __syncthreads();

#pragma unroll
        for (int kk = 0; kk < 32; kk++) {
            float a[4], b[4];
#pragma unroll
            for (int i = 0; i < 4; i++) a[i] = sW[ty + 16 * i][kk];
#pragma unroll
            for (int j = 0; j < 4; j++) b[j] = sX[kk][tx + 16 * j];
#pragma unroll
            for (int i = 0; i < 4; i++)
#pragma unroll
                for (int j = 0; j < 4; j++) acc[i][j] += a[i] * b[j];
        }
        __syncthreads();
    }

#pragma unroll
    for (int i = 0; i < 4; i++) {
        int o = o0 + ty + 16 * i;
        float bias = (o < 512) ? bq[o] : bkv[o - 512];
        float* dst;
        if (o < 512) {
            int h = o >> 6, d = o & 63;
            dst = g_q + (((size_t)n * HDS + h) * DQK + d) * TT;
        } else if (o < 1024) {
            int oo = o - 512, h = oo >> 6, d = oo & 63;
            dst = g_k + (((size_t)n * HDS + h) * DQK + d) * TT;
        } else {
            int oo = o - 1024, h = oo >> 5, d = oo & 31;
            dst = g_v + (((size_t)n * HDS + h) * DV + d) * TT;
        }
#pragma unroll
        for (int j = 0; j < 4; j++) {
            int t = t0 + tx + 16 * j;
            dst[t] = acc[i][j] + bias;   // coalesced: consecutive tx -> consecutive t
        }
    }
}

// ---------------------------------------------------------------------------
// Kernel 2: flash-style causal attention.
// grid: (T/64 q-tiles, NB*HDS), block 256.
// Q tile held in smem; stream K/V tiles; online softmax; P reuses sK.
// Output ao[n][h*32+dv][t] for the out-projection GEMM.
// ---------------------------------------------------------------------------
__global__ __launch_bounds__(256) void attn_kernel()
{
    __shared__ float sQ[64][65];
    __shared__ float sK[64][65];   // reused for P after S is computed
    __shared__ float sV[64][33];

    const int nh = blockIdx.y;     // n*8 + h
    const int qb = blockIdx.x;
    const int tid = threadIdx.x;
    const int ty = tid >> 4, tx = tid & 15;
    const float scale = 0.125f;    // 1/sqrt(64)

    const float* __restrict__ qp = g_q + (size_t)nh * DQK * TT;  // [d][t]
    const float* __restrict__ kp = g_k + (size_t)nh * DQK * TT;
    const float* __restrict__ vp = g_v + (size_t)nh * DV * TT;

    const int t0 = qb * 64;

    // Load Q tile transposed: sQ[t_local][d]
#pragma unroll
    for (int i = 0; i < 16; i++) {
        int idx = tid + i * 256;
        int tl = idx & 63, d = idx >> 6;
        sQ[tl][d] = qp[(size_t)d * TT + t0 + tl];
    }

    float m[4], l[4], O[4][2];
#pragma unroll
    for (int i = 0; i < 4; i++) {
        m[i] = -1e30f; l[i] = 0.f; O[i][0] = 0.f; O[i][1] = 0.f;
    }

    for (int kb = 0; kb <= qb; kb++) {
        __syncthreads();           // prev iter done reading sK(P)/sV; sQ stores visible
        const int s0 = kb * 64;
#pragma unroll
        for (int i = 0; i < 16; i++) {
            int idx = tid + i * 256;
            int sl = idx & 63, d = idx >> 6;
            sK[sl][d] = kp[(size_t)d * TT + s0 + sl];
        }
#pragma unroll
        for (int i = 0; i < 8; i++) {
            int idx = tid + i * 256;
            int sl = idx & 63, d = idx >> 6;
            sV[sl][d] = vp[(size_t)d * TT + s0 + sl];
        }
        __syncthreads();

        // S = Q @ K^T  (64x64), strided 4x4 per thread
        float S[4][4];
#pragma unroll
        for (int i = 0; i < 4; i++)
#pragma unroll
            for (int j = 0; j < 4; j++) S[i][j] = 0.f;

#pragma unroll 8
        for (int kk = 0; kk < DQK; kk++) {
            float a[4], b[4];
#pragma unroll
            for (int i = 0; i < 4; i++) a[i] = sQ[ty + 16 * i][kk];
#pragma unroll
            for (int j = 0; j < 4; j++) b[j] = sK[tx + 16 * j][kk];
#pragma unroll
            for (int i = 0; i < 4; i++)
#pragma unroll
                for (int j = 0; j < 4; j++) S[i][j] += a[i] * b[j];
        }

        const bool diag = (kb == qb);
#pragma unroll
        for (int i = 0; i < 4; i++) {
            int t = t0 + ty + 16 * i;
#pragma unroll
            for (int j = 0; j < 4; j++) {
                int s = s0 + tx + 16 * j;
                float v = S[i][j] * scale;
                if (diag && s > t) v = -1e30f;
                S[i][j] = v;
            }
        }

        // online softmax
        float mnew[4];
#pragma unroll
        for (int i = 0; i < 4; i++) {
            mnew[i] = fmaxf(fmaxf(S[i][0], S[i][1]), fmaxf(S[i][2], S[i][3]));
        }
#pragma unroll
        for (int off = 8; off >= 1; off >>= 1)
#pragma unroll
            for (int i = 0; i < 4; i++)
                mnew[i] = fmaxf(mnew[i], __shfl_xor_sync(0xffffffffu, mnew[i], off));

        float alpha[4], rs[4];
#pragma unroll
        for (int i = 0; i < 4; i++) {
            float mi = fmaxf(m[i], mnew[i]);
            alpha[i] = __expf(m[i] - mi);
            m[i] = mi;
            rs[i] = 0.f;
        }
#pragma unroll
        for (int i = 0; i < 4; i++)
#pragma unroll
            for (int j = 0; j < 4; j++) {
                float p = __expf(S[i][j] - m[i]);
                S[i][j] = p;
                rs[i] += p;
            }
#pragma unroll
        for (int off = 8; off >= 1; off >>= 1)
#pragma unroll
            for (int i = 0; i < 4; i++)
                rs[i] += __shfl_xor_sync(0xffffffffu, rs[i], off);
#pragma unroll
        for (int i = 0; i < 4; i++) l[i] = l[i] * alpha[i] + rs[i];

        __syncthreads();           // everyone done reading sK as K
#pragma unroll
        for (int i = 0; i < 4; i++)
#pragma unroll
            for (int j = 0; j < 4; j++)
                sK[ty + 16 * i][tx + 16 * j] = S[i][j];   // P -> sK
        __syncthreads();

        // O = O*alpha + P @ V  (64x32), thread cols {tx, tx+16}
#pragma unroll
        for (int i = 0; i < 4; i++) { O[i][0] *= alpha[i]; O[i][1] *= alpha[i]; }
#pragma unroll 8
        for (int ss = 0; ss < 64; ss++) {
            float v0 = sV[ss][tx], v1 = sV[ss][tx + 16];
#pragma unroll
            for (int i = 0; i < 4; i++) {
                float p = sK[ty + 16 * i][ss];
                O[i][0] += p * v0;
                O[i][1] += p * v1;
            }
        }
    }

    // write ao[n][h*32+dv][t]
    const int n = nh >> 3, h = nh & 7;
    float* __restrict__ aob = g_ao + ((size_t)n * OCH + h * DV) * TT;
#pragma unroll
    for (int i = 0; i < 4; i++) {
        int t = t0 + ty + 16 * i;
        float inv = 1.f / l[i];
        aob[(size_t)tx * TT + t]        = O[i][0] * inv;
        aob[(size_t)(tx + 16) * TT + t] = O[i][1] * inv;
    }
}

// ---------------------------------------------------------------------------
// Kernel 3: output projection.
// out[n][o][t] = sum_c Wo[o][c] * ao[n][c][t] + bo[o]
// grid: (T/64, 256/64, NB), block 256
// ---------------------------------------------------------------------------
__global__ __launch_bounds__(256) void out_proj_kernel(
    const float* __restrict__ Wo, const float* __restrict__ bo,
    float* __restrict__ out)
{
    __shared__ float sW[64][33];
    __shared__ float sX[32][65];

    const int n  = blockIdx.z;
    const int o0 = blockIdx.y * 64;
    const int t0 = blockIdx.x * 64;
    const int tid = threadIdx.x;
    const int ty = tid >> 4, tx = tid & 15;

    const float* __restrict__ xb = g_ao + (size_t)n * OCH * TT;

    float acc[4][4];
#pragma unroll
    for (int i = 0; i < 4; i++)
#pragma unroll
        for (int j = 0; j < 4; j++) acc[i][j] = 0.f;

    for (int k0 = 0; k0 < OCH; k0 += 32) {
#pragma unroll
        for (int i = 0; i < 8; i++) {
            int idx = tid + i * 256;
            int r = idx >> 5, c = idx & 31;
            sW[r][c] = Wo[(size_t)(o0 + r) * OCH + k0 + c];
        }
#pragma unroll
        for (int i = 0; i < 8; i++) {
            int idx = tid + i * 256;
            int r = idx >> 6, c = idx & 63;
            sX[r][c] = xb[(size_t)(k0 + r) * TT + t0 + c];
        }
        __syncthreads();

#pragma unroll
        for (int kk = 0; kk < 32; kk++) {
            float a[4], b[4];
#pragma unroll
            for (int i = 0; i < 4; i++) a[i] = sW[ty + 16 * i][kk];
#pragma unroll
            for (int j = 0; j < 4; j++) b[j] = sX[kk][tx + 16 * j];
#pragma unroll
            for (int i = 0; i < 4; i++)
#pragma unroll
                for (int j = 0; j < 4; j++) acc[i][j] += a[i] * b[j];
        }
        __syncthreads();
    }

#pragma unroll
    for (int i = 0; i < 4; i++) {
        int o = o0 + ty + 16 * i;
        float bias = bo[o];
        float* dst = out + ((size_t)n * OCH + o) * TT;
#pragma unroll
        for (int j = 0; j < 4; j++) {
            int t = t0 + tx + 16 * j;
            dst[t] = acc[i][j] + bias;
        }
    }
}

// ---------------------------------------------------------------------------
extern "C" void kernel_launch(void* const* d_in, const int* in_sizes, int n_in,
                              void* d_out, int out_size)
{
    const float* x   = (const float*)d_in[0];
    const float* Wq  = (const float*)d_in[1];
    const float* bq  = (const float*)d_in[2];
    const float* Wkv = (const float*)d_in[3];
    const float* bkv = (const float*)d_in[4];
    const float* Wo  = (const float*)d_in[5];
    const float* bo  = (const float*)d_in[6];
    float* out = (float*)d_out;

    qkv_kernel<<<dim3(TT / 64, 1280 / 64, NB), 256>>>(x, Wq, bq, Wkv, bkv);
    attn_kernel<<<dim3(TT / 64, NB * HDS), 256>>>();
    out_proj_kernel<<<dim3(TT / 64, OCH / 64, NB), 256>>>(Wo, bo, out);
}

// round 3
// speedup vs baseline: 1.3344x; 1.3344x over previous
#include <cuda_runtime.h>

#define NB   8
#define CIN  256
#define TT   1024
#define HDS  8
#define DQK  64
#define DV   32
#define OCH  256

// Scratch (allocation-free rule: __device__ globals)
__device__ float g_q[NB * HDS * DQK * TT];   // [n][h][d][t]
__device__ float g_k[NB * HDS * DQK * TT];   // [n][h][d][t]
__device__ float g_v[NB * HDS * DV  * TT];   // [n][h][dv][t]
__device__ float g_ao[NB * OCH * TT];        // [n][c=h*32+dv][t]

// ---------------------------------------------------------------------------
// Kernel 1: fused QKV projection. 128x128 tile, 256 threads, 8x8 per thread.
// y[n][o][t] = sum_c W[o][c] * x[n][c][t] + b[o],  o in [0,1280)
// grid: (T/128, 1280/128, NB)
// ---------------------------------------------------------------------------
__global__ __launch_bounds__(256) void qkv_kernel(
    const float* __restrict__ x, const float* __restrict__ Wq,
    const float* __restrict__ bq, const float* __restrict__ Wkv,
    const float* __restrict__ bkv)
{
    __shared__ float sW[16][132];   // [k][o_local], 132*4=528B row stride (16B mult)
    __shared__ float sX[16][132];   // [k][t_local]

    const int n  = blockIdx.z;
    const int o0 = blockIdx.y * 128;
    const int t0 = blockIdx.x * 128;
    const int tid = threadIdx.x;
    const int tx = tid & 15, ty = tid >> 4;

    const float* __restrict__ xb = x + (size_t)n * CIN * TT;

    float acc[8][8];
#pragma unroll
    for (int i = 0; i < 8; i++)
#pragma unroll
        for (int j = 0; j < 8; j++) acc[i][j] = 0.f;

    for (int k0 = 0; k0 < CIN; k0 += 16) {
        // W tile: 128 o x 16 k -> transposed into sW[k][o]
#pragma unroll
        for (int u = 0; u < 2; u++) {
            int idx = tid + u * 256;          // [0,512): 4 float4 per o-row
            int o = idx >> 2, kq = idx & 3;
            int go = o0 + o;
            const float* src = (go < 512) ? (Wq + (size_t)go * CIN)
                                          : (Wkv + (size_t)(go - 512) * CIN);
            float4 w = *(const float4*)(src + k0 + kq * 4);
            sW[kq * 4 + 0][o] = w.x;
            sW[kq * 4 + 1][o] = w.y;
            sW[kq * 4 + 2][o] = w.z;
            sW[kq * 4 + 3][o] = w.w;
        }
        // X tile: 16 k x 128 t, direct float4
#pragma unroll
        for (int u = 0; u < 2; u++) {
            int idx = tid + u * 256;          // [0,512): 32 float4 per k-row
            int k = idx >> 5, tq = idx & 31;
            float4 v = *(const float4*)(xb + (size_t)(k0 + k) * TT + t0 + tq * 4);
            *(float4*)&sX[k][tq * 4] = v;
        }
        __syncthreads();

#pragma unroll
        for (int kk = 0; kk < 16; kk++) {
            float4 a0 = *(float4*)&sW[kk][ty * 4];
            float4 a1 = *(float4*)&sW[kk][ty * 4 + 64];
            float4 b0 = *(float4*)&sX[kk][tx * 4];
            float4 b1 = *(float4*)&sX[kk][tx * 4 + 64];
            float av[8] = {a0.x, a0.y, a0.z, a0.w, a1.x, a1.y, a1.z, a1.w};
            float bv[8] = {b0.x, b0.y, b0.z, b0.w, b1.x, b1.y, b1.z, b1.w};
#pragma unroll
            for (int i = 0; i < 8; i++)
#pragma unroll
                for (int j = 0; j < 8; j++) acc[i][j] += av[i] * bv[j];
        }
        __syncthreads();
    }

#pragma unroll
    for (int i = 0; i < 8; i++) {
        int o = o0 + (i & 3) + ty * 4 + ((i >= 4) ? 64 : 0);
        float bias;
        float* dst;
        if (o < 512) {
            int h = o >> 6, d = o & 63;
            bias = bq[o];
            dst = g_q + (((size_t)n * HDS + h) * DQK + d) * TT;
        } else if (o < 1024) {
            int oo = o - 512, h = oo >> 6, d = oo & 63;
            bias = bkv[o - 512];
            dst = g_k + (((size_t)n * HDS + h) * DQK + d) * TT;
        } else {
            int oo = o - 1024, h = oo >> 5, d = oo & 31;
            bias = bkv[o - 512];
            dst = g_v + (((size_t)n * HDS + h) * DV + d) * TT;
        }
        float4 v0 = make_float4(acc[i][0] + bias, acc[i][1] + bias,
                                acc[i][2] + bias, acc[i][3] + bias);
        float4 v1 = make_float4(acc[i][4] + bias, acc[i][5] + bias,
                                acc[i][6] + bias, acc[i][7] + bias);
        *(float4*)(dst + t0 + tx * 4)      = v0;
        *(float4*)(dst + t0 + 64 + tx * 4) = v1;
    }
}

// ---------------------------------------------------------------------------
// Kernel 2: flash-style causal attention, fully vectorized.
// smem layouts: sQ[d][t], sKP = K[d][s] then P[s][t], sV[s][dv].
// grid: (T/64, NB*HDS), block 256 (16x16), 4x4 contiguous micro-tile.
// ---------------------------------------------------------------------------
__global__ __launch_bounds__(256) void attn_kernel()
{
    __shared__ float sQ[64][68];    // 68*4=272B (16B mult)
    __shared__ float sKP[64][68];   // K as [d][s]; reused for P as [s][t]
    __shared__ float sV[64][36];    // [s][dv], 36*4=144B (8B mult, float2 ok)

    const int nh = blockIdx.y;
    const int qb = blockIdx.x;
    const int tid = threadIdx.x;
    const int tx = tid & 15, ty = tid >> 4;
    const float scale = 0.125f;

    const float* __restrict__ qp = g_q + (size_t)nh * DQK * TT;
    const float* __restrict__ kp = g_k + (size_t)nh * DQK * TT;
    const float* __restrict__ vp = g_v + (size_t)nh * DV * TT;

    const int t0 = qb * 64;

    // Q tile [d][t]: 64x64 = 1024 float4
#pragma unroll
    for (int u = 0; u < 4; u++) {
        int idx = tid + u * 256;
        int d = idx >> 4, tq = idx & 15;
        *(float4*)&sQ[d][tq * 4] = *(const float4*)(qp + (size_t)d * TT + t0 + tq * 4);
    }

    float m[4], l[4], O[4][2];
#pragma unroll
    for (int i = 0; i < 4; i++) { m[i] = -1e30f; l[i] = 0.f; O[i][0] = 0.f; O[i][1] = 0.f; }

    for (int kb = 0; kb <= qb; kb++) {
        __syncthreads();
        const int s0 = kb * 64;
        // K tile [d][s]
#pragma unroll
        for (int u = 0; u < 4; u++) {
            int idx = tid + u * 256;
            int d = idx >> 4, sq = idx & 15;
            *(float4*)&sKP[d][sq * 4] = *(const float4*)(kp + (size_t)d * TT + s0 + sq * 4);
        }
        // V tile: transpose [dv][t] -> [s][dv]
#pragma unroll
        for (int u = 0; u < 2; u++) {
            int idx = tid + u * 256;
            int dv = idx >> 4, sq = idx & 15;
            float4 v = *(const float4*)(vp + (size_t)dv * TT + s0 + sq * 4);
            sV[sq * 4 + 0][dv] = v.x;
            sV[sq * 4 + 1][dv] = v.y;
            sV[sq * 4 + 2][dv] = v.z;
            sV[sq * 4 + 3][dv] = v.w;
        }
        __syncthreads();

        // S = Q^T K  (rows: q-index ty*4+i, cols: s-index tx*4+j)
        float S[4][4];
#pragma unroll
        for (int i = 0; i < 4; i++)
#pragma unroll
            for (int j = 0; j < 4; j++) S[i][j] = 0.f;

#pragma unroll 8
        for (int kk = 0; kk < DQK; kk++) {
            float4 a = *(float4*)&sQ[kk][ty * 4];
            float4 b = *(float4*)&sKP[kk][tx * 4];
            float av[4] = {a.x, a.y, a.z, a.w};
            float bv[4] = {b.x, b.y, b.z, b.w};
#pragma unroll
            for (int i = 0; i < 4; i++)
#pragma unroll
                for (int j = 0; j < 4; j++) S[i][j] += av[i] * bv[j];
        }

        const bool diag = (kb == qb);
#pragma unroll
        for (int i = 0; i < 4; i++) {
            int t = t0 + ty * 4 + i;
#pragma unroll
            for (int j = 0; j < 4; j++) {
                int s = s0 + tx * 4 + j;
                float v = S[i][j] * scale;
                if (diag && s > t) v = -1e30f;
                S[i][j] = v;
            }
        }

        // online softmax (rows owned by same-ty lanes; reduce across 16 tx lanes)
        float mnew[4];
#pragma unroll
        for (int i = 0; i < 4; i++)
            mnew[i] = fmaxf(fmaxf(S[i][0], S[i][1]), fmaxf(S[i][2], S[i][3]));
#pragma unroll
        for (int off = 8; off >= 1; off >>= 1)
#pragma unroll
            for (int i = 0; i < 4; i++)
                mnew[i] = fmaxf(mnew[i], __shfl_xor_sync(0xffffffffu, mnew[i], off));

        float alpha[4], rs[4];
#pragma unroll
        for (int i = 0; i < 4; i++) {
            float mi = fmaxf(m[i], mnew[i]);
            alpha[i] = __expf(m[i] - mi);
            m[i] = mi;
            rs[i] = 0.f;
        }
#pragma unroll
        for (int i = 0; i < 4; i++)
#pragma unroll
            for (int j = 0; j < 4; j++) {
                float p = __expf(S[i][j] - m[i]);
                S[i][j] = p;
                rs[i] += p;
            }
#pragma unroll
        for (int off = 8; off >= 1; off >>= 1)
#pragma unroll
            for (int i = 0; i < 4; i++)
                rs[i] += __shfl_xor_sync(0xffffffffu, rs[i], off);
#pragma unroll
        for (int i = 0; i < 4; i++) l[i] = l[i] * alpha[i] + rs[i];

        __syncthreads();            // done reading sKP as K
        // P -> sKP as [s][t]; pack rows i into float4 per column j
#pragma unroll
        for (int j = 0; j < 4; j++) {
            float4 pv = make_float4(S[0][j], S[1][j], S[2][j], S[3][j]);
            *(float4*)&sKP[tx * 4 + j][ty * 4] = pv;
        }
        __syncthreads();

        // O = O*alpha + P @ V ; thread cols dv = tx*2, tx*2+1
#pragma unroll
        for (int i = 0; i < 4; i++) { O[i][0] *= alpha[i]; O[i][1] *= alpha[i]; }
#pragma unroll 8
        for (int ss = 0; ss < 64; ss++) {
            float4 p = *(float4*)&sKP[ss][ty * 4];
            float2 v = *(float2*)&sV[ss][tx * 2];
            float pv_[4] = {p.x, p.y, p.z, p.w};
#pragma unroll
            for (int i = 0; i < 4; i++) {
                O[i][0] += pv_[i] * v.x;
                O[i][1] += pv_[i] * v.y;
            }
        }
    }

    // write ao[n][h*32+dv][t] with vectorized stores along t
    const int n = nh >> 3, h = nh & 7;
    float* __restrict__ aob = g_ao + ((size_t)n * OCH + h * DV) * TT;
    float inv[4];
#pragma unroll
    for (int i = 0; i < 4; i++) inv[i] = 1.f / l[i];
    float4 o0v = make_float4(O[0][0] * inv[0], O[1][0] * inv[1],
                             O[2][0] * inv[2], O[3][0] * inv[3]);
    float4 o1v = make_float4(O[0][1] * inv[0], O[1][1] * inv[1],
                             O[2][1] * inv[2], O[3][1] * inv[3]);
    *(float4*)(aob + (size_t)(tx * 2) * TT + t0 + ty * 4)     = o0v;
    *(float4*)(aob + (size_t)(tx * 2 + 1) * TT + t0 + ty * 4) = o1v;
}

// ---------------------------------------------------------------------------
// Kernel 3: output projection. Same 128x128 / 8x8 structure.
// grid: (T/128, 256/128, NB)
// ---------------------------------------------------------------------------
__global__ __launch_bounds__(256) void out_proj_kernel(
    const float* __restrict__ Wo, const float* __restrict__ bo,
    float* __restrict__ out)
{
    __shared__ float sW[16][132];
    __shared__ float sX[16][132];

    const int n  = blockIdx.z;
    const int o0 = blockIdx.y * 128;
    const int t0 = blockIdx.x * 128;
    const int tid = threadIdx.x;
    const int tx = tid & 15, ty = tid >> 4;

    const float* __restrict__ xb = g_ao + (size_t)n * OCH * TT;

    float acc[8][8];
#pragma unroll
    for (int i = 0; i < 8; i++)
#pragma unroll
        for (int j = 0; j < 8; j++) acc[i][j] = 0.f;

    for (int k0 = 0; k0 < OCH; k0 += 16) {
#pragma unroll
        for (int u = 0; u < 2; u++) {
            int idx = tid + u * 256;
            int o = idx >> 2, kq = idx & 3;
            float4 w = *(const float4*)(Wo + (size_t)(o0 + o) * OCH + k0 + kq * 4);
            sW[kq * 4 + 0][o] = w.x;
            sW[kq * 4 + 1][o] = w.y;
            sW[kq * 4 + 2][o] = w.z;
            sW[kq * 4 + 3][o] = w.w;
        }
#pragma unroll
        for (int u = 0; u < 2; u++) {
            int idx = tid + u * 256;
            int k = idx >> 5, tq = idx & 31;
            float4 v = *(const float4*)(xb + (size_t)(k0 + k) * TT + t0 + tq * 4);
            *(float4*)&sX[k][tq * 4] = v;
        }
        __syncthreads();

#pragma unroll
        for (int kk = 0; kk < 16; kk++) {
            float4 a0 = *(float4*)&sW[kk][ty * 4];
            float4 a1 = *(float4*)&sW[kk][ty * 4 + 64];
            float4 b0 = *(float4*)&sX[kk][tx * 4];
            float4 b1 = *(float4*)&sX[kk][tx * 4 + 64];
            float av[8] = {a0.x, a0.y, a0.z, a0.w, a1.x, a1.y, a1.z, a1.w};
            float bv[8] = {b0.x, b0.y, b0.z, b0.w, b1.x, b1.y, b1.z, b1.w};
#pragma unroll
            for (int i = 0; i < 8; i++)
#pragma unroll
                for (int j = 0; j < 8; j++) acc[i][j] += av[i] * bv[j];
        }
        __syncthreads();
    }

#pragma unroll
    for (int i = 0; i < 8; i++) {
        int o = o0 + (i & 3) + ty * 4 + ((i >= 4) ? 64 : 0);
        float bias = bo[o];
        float* dst = out + ((size_t)n * OCH + o) * TT;
        float4 v0 = make_float4(acc[i][0] + bias, acc[i][1] + bias,
                                acc[i][2] + bias, acc[i][3] + bias);
        float4 v1 = make_float4(acc[i][4] + bias, acc[i][5] + bias,
                                acc[i][6] + bias, acc[i][7] + bias);
        *(float4*)(dst + t0 + tx * 4)      = v0;
        *(float4*)(dst + t0 + 64 + tx * 4) = v1;
    }
}

// ---------------------------------------------------------------------------
extern "C" void kernel_launch(void* const* d_in, const int* in_sizes, int n_in,
                              void* d_out, int out_size)
{
    const float* x   = (const float*)d_in[0];
    const float* Wq  = (const float*)d_in[1];
    const float* bq  = (const float*)d_in[2];
    const float* Wkv = (const float*)d_in[3];
    const float* bkv = (const float*)d_in[4];
    const float* Wo  = (const float*)d_in[5];
    const float* bo  = (const float*)d_in[6];
    float* out = (float*)d_out;

    qkv_kernel<<<dim3(TT / 128, 1280 / 128, NB), 256>>>(x, Wq, bq, Wkv, bkv);
    attn_kernel<<<dim3(TT / 64, NB * HDS), 256>>>();
    out_proj_kernel<<<dim3(TT / 128, OCH / 128, NB), 256>>>(Wo, bo, out);
}

// round 4
// speedup vs baseline: 2.9394x; 2.2028x over previous
#include <cuda_runtime.h>
#include <cstdint>

#define NB   8
#define CIN  256
#define TT   1024
#define HDS  8
#define DQK  64
#define DV   32
#define OCH  256

// Scratch (allocation-free rule: __device__ globals)
__device__ float g_q[NB * HDS * DQK * TT];   // [n][h][d][t]
__device__ float g_k[NB * HDS * DQK * TT];   // [n][h][d][t]
__device__ float g_v[NB * HDS * DV  * TT];   // [n][h][dv][t]
__device__ float g_ao[NB * OCH * TT];        // [n][c=h*32+dv][t]

// ---------------------------------------------------------------------------
// tf32 helpers
// ---------------------------------------------------------------------------
__device__ __forceinline__ uint32_t f2tf(float f) {
    uint32_t u;
    asm("cvt.rna.tf32.f32 %0, %1;" : "=r"(u) : "f"(f));
    return u;
}

// D(16x8) += A(16x8,row) * B(8x8,col), tf32 in, f32 accum
__device__ __forceinline__ void mma8(float* d, const uint32_t* a,
                                     uint32_t b0, uint32_t b1) {
    asm volatile(
        "mma.sync.aligned.m16n8k8.row.col.f32.tf32.tf32.f32 "
        "{%0,%1,%2,%3}, {%4,%5,%6,%7}, {%8,%9}, {%0,%1,%2,%3};\n"
        : "+f"(d[0]), "+f"(d[1]), "+f"(d[2]), "+f"(d[3])
        : "r"(a[0]), "r"(a[1]), "r"(a[2]), "r"(a[3]), "r"(b0), "r"(b1));
}

// ---------------------------------------------------------------------------
// Kernel 1: fused QKV projection via tf32 mma. 128o x 128t tile, K=256.
// 8 warps: (wo 0..3) x (wt 0..1); warp tile 32o x 64t.
// A = W [o][k] (row-major), B = X [k][t] (col-major-B).
// grid: (T/128, 1280/128, NB)
// ---------------------------------------------------------------------------
__global__ __launch_bounds__(256) void qkv_kernel(
    const float* __restrict__ x, const float* __restrict__ Wq,
    const float* __restrict__ bq, const float* __restrict__ Wkv,
    const float* __restrict__ bkv)
{
    __shared__ uint32_t sA[128 * 36];   // [o][k32], pad 36: banks 4r+c distinct
    __shared__ uint32_t sB[32 * 136];   // [k32][t128], pad 136: banks 8k+n distinct

    const int n  = blockIdx.z;
    const int o0 = blockIdx.y * 128;
    const int t0 = blockIdx.x * 128;
    const int tid = threadIdx.x;
    const int lane = tid & 31, wid = tid >> 5;
    const int wo = wid >> 1, wt = wid & 1;
    const int lr = lane >> 2, lc = lane & 3;

    const float* __restrict__ xb = x + (size_t)n * CIN * TT;

    float d[2][8][4];
#pragma unroll
    for (int mi = 0; mi < 2; mi++)
#pragma unroll
        for (int j = 0; j < 8; j++)
#pragma unroll
            for (int q = 0; q < 4; q++) d[mi][j][q] = 0.f;

    for (int k0 = 0; k0 < CIN; k0 += 32) {
        __syncthreads();
        // A fill: W[o0+o][k0..k0+31] -> sA[o][k] (tf32)
#pragma unroll
        for (int u = 0; u < 4; u++) {
            int idx = tid + u * 256;
            int o = idx >> 3, kq = idx & 7;
            int go = o0 + o;
            const float* src = (go < 512)
                ? (Wq  + (size_t)go * CIN + k0 + kq * 4)
                : (Wkv + (size_t)(go - 512) * CIN + k0 + kq * 4);
            float4 w = *(const float4*)src;
            uint32_t* p = &sA[o * 36 + kq * 4];
            p[0] = f2tf(w.x); p[1] = f2tf(w.y); p[2] = f2tf(w.z); p[3] = f2tf(w.w);
        }
        // B fill: x[k0+k][t0..t0+127] -> sB[k][t] (tf32)
#pragma unroll
        for (int u = 0; u < 4; u++) {
            int idx = tid + u * 256;
            int k = idx >> 5, tq = idx & 31;
            float4 v = *(const float4*)(xb + (size_t)(k0 + k) * TT + t0 + tq * 4);
            uint32_t* p = &sB[k * 136 + tq * 4];
            p[0] = f2tf(v.x); p[1] = f2tf(v.y); p[2] = f2tf(v.z); p[3] = f2tf(v.w);
        }
        __syncthreads();

#pragma unroll
        for (int kk = 0; kk < 4; kk++) {
            const int kc = kk * 8;
            uint32_t a[2][4];
#pragma unroll
            for (int mi = 0; mi < 2; mi++) {
                int row = wo * 32 + mi * 16 + lr;
                a[mi][0] = sA[row * 36 + kc + lc];
                a[mi][1] = sA[(row + 8) * 36 + kc + lc];
                a[mi][2] = sA[row * 36 + kc + 4 + lc];
                a[mi][3] = sA[(row + 8) * 36 + kc + 4 + lc];
            }
#pragma unroll
            for (int j = 0; j < 8; j++) {
                int col = wt * 64 + j * 8 + lr;
                uint32_t b0 = sB[(kc + lc) * 136 + col];
                uint32_t b1 = sB[(kc + 4 + lc) * 136 + col];
                mma8(d[0][j], a[0], b0, b1);
                mma8(d[1][j], a[1], b0, b1);
            }
        }
    }

    // epilogue: route rows to g_q / g_k / g_v
#pragma unroll
    for (int mi = 0; mi < 2; mi++) {
#pragma unroll
        for (int half = 0; half < 2; half++) {
            int o = o0 + wo * 32 + mi * 16 + half * 8 + lr;
            float bias;
            float* dst;
            if (o < 512) {
                int h = o >> 6, dd = o & 63;
                bias = bq[o];
                dst = g_q + (((size_t)n * HDS + h) * DQK + dd) * TT;
            } else if (o < 1024) {
                int oo = o - 512, h = oo >> 6, dd = oo & 63;
                bias = bkv[o - 512];
                dst = g_k + (((size_t)n * HDS + h) * DQK + dd) * TT;
            } else {
                int oo = o - 1024, h = oo >> 5, dd = oo & 31;
                bias = bkv[o - 512];
                dst = g_v + (((size_t)n * HDS + h) * DV + dd) * TT;
            }
#pragma unroll
            for (int j = 0; j < 8; j++) {
                int t = t0 + wt * 64 + j * 8 + lc * 2;
                dst[t]     = d[mi][j][half * 2 + 0] + bias;
                dst[t + 1] = d[mi][j][half * 2 + 1] + bias;
            }
        }
    }
}

// ---------------------------------------------------------------------------
// Kernel 2: flash attention via tf32 mma.
// Block 128 thr (4 warps), q-tile 64, warp owns 16 q-rows x full 64 s.
// sQ[t][d], sKP: K[d][s] (stride 72) then P[t][s] (stride 68), sV[s][dv].
// grid: (T/64, NB*HDS)
// ---------------------------------------------------------------------------
__global__ __launch_bounds__(128) void attn_kernel()
{
    __shared__ uint32_t sQ[64 * 68];
    __shared__ uint32_t sKP[64 * 72];
    __shared__ uint32_t sV[64 * 40];

    const int nh = blockIdx.y;
    const int qb = blockIdx.x;
    const int tid = threadIdx.x;
    const int lane = tid & 31, w = tid >> 5;
    const int lr = lane >> 2, lc = lane & 3;
    const float scale = 0.125f;

    const float* __restrict__ qp = g_q + (size_t)nh * DQK * TT;
    const float* __restrict__ kp = g_k + (size_t)nh * DQK * TT;
    const float* __restrict__ vp = g_v + (size_t)nh * DV * TT;

    const int t0 = qb * 64;

    // Q fill: [d][t] global -> sQ[t][d] tf32
#pragma unroll
    for (int u = 0; u < 8; u++) {
        int idx = tid + u * 128;
        int dd = idx >> 4, tq = idx & 15;
        float4 v = *(const float4*)(qp + (size_t)dd * TT + t0 + tq * 4);
        sQ[(tq * 4 + 0) * 68 + dd] = f2tf(v.x);
        sQ[(tq * 4 + 1) * 68 + dd] = f2tf(v.y);
        sQ[(tq * 4 + 2) * 68 + dd] = f2tf(v.z);
        sQ[(tq * 4 + 3) * 68 + dd] = f2tf(v.w);
    }

    float m0 = -1e30f, m1 = -1e30f, l0 = 0.f, l1 = 0.f;
    float o_[4][4];
#pragma unroll
    for (int j = 0; j < 4; j++)
#pragma unroll
        for (int q = 0; q < 4; q++) o_[j][q] = 0.f;

    for (int kb = 0; kb <= qb; kb++) {
        __syncthreads();
        const int s0 = kb * 64;
        // K fill: [d][s] direct
#pragma unroll
        for (int u = 0; u < 8; u++) {
            int idx = tid + u * 128;
            int dd = idx >> 4, sq = idx & 15;
            float4 v = *(const float4*)(kp + (size_t)dd * TT + s0 + sq * 4);
            uint32_t* p = &sKP[dd * 72 + sq * 4];
            p[0] = f2tf(v.x); p[1] = f2tf(v.y); p[2] = f2tf(v.z); p[3] = f2tf(v.w);
        }
        // V fill: [dv][t] global -> sV[s][dv]
#pragma unroll
        for (int u = 0; u < 4; u++) {
            int idx = tid + u * 128;
            int dv = idx >> 4, sq = idx & 15;
            float4 v = *(const float4*)(vp + (size_t)dv * TT + s0 + sq * 4);
            sV[(sq * 4 + 0) * 40 + dv] = f2tf(v.x);
            sV[(sq * 4 + 1) * 40 + dv] = f2tf(v.y);
            sV[(sq * 4 + 2) * 40 + dv] = f2tf(v.z);
            sV[(sq * 4 + 3) * 40 + dv] = f2tf(v.w);
        }
        __syncthreads();

        // S = Q K^T : 16 x 64 per warp, 8 n-frags
        float s[8][4];
#pragma unroll
        for (int j = 0; j < 8; j++)
#pragma unroll
            for (int q = 0; q < 4; q++) s[j][q] = 0.f;

#pragma unroll
        for (int ks = 0; ks < 8; ks++) {
            const int kd = ks * 8;
            uint32_t a[4];
            a[0] = sQ[(w * 16 + lr) * 68 + kd + lc];
            a[1] = sQ[(w * 16 + lr + 8) * 68 + kd + lc];
            a[2] = sQ[(w * 16 + lr) * 68 + kd + 4 + lc];
            a[3] = sQ[(w * 16 + lr + 8) * 68 + kd + 4 + lc];
#pragma unroll
            for (int j = 0; j < 8; j++) {
                uint32_t b0 = sKP[(kd + lc) * 72 + j * 8 + lr];
                uint32_t b1 = sKP[(kd + 4 + lc) * 72 + j * 8 + lr];
                mma8(s[j], a, b0, b1);
            }
        }

        // scale + causal mask
        const int tg0 = t0 + w * 16 + lr, tg1 = tg0 + 8;
        const bool diag = (kb == qb);
#pragma unroll
        for (int j = 0; j < 8; j++) {
            int sg = s0 + j * 8 + lc * 2;
            s[j][0] *= scale; s[j][1] *= scale; s[j][2] *= scale; s[j][3] *= scale;
            if (diag) {
                if (sg     > tg0) s[j][0] = -1e30f;
                if (sg + 1 > tg0) s[j][1] = -1e30f;
                if (sg     > tg1) s[j][2] = -1e30f;
                if (sg + 1 > tg1) s[j][3] = -1e30f;
            }
        }

        // online softmax (rows tg0, tg1 owned by this lane-quad)
        float mn0 = -1e30f, mn1 = -1e30f;
#pragma unroll
        for (int j = 0; j < 8; j++) {
            mn0 = fmaxf(mn0, fmaxf(s[j][0], s[j][1]));
            mn1 = fmaxf(mn1, fmaxf(s[j][2], s[j][3]));
        }
        mn0 = fmaxf(mn0, __shfl_xor_sync(0xffffffffu, mn0, 1));
        mn0 = fmaxf(mn0, __shfl_xor_sync(0xffffffffu, mn0, 2));
        mn1 = fmaxf(mn1, __shfl_xor_sync(0xffffffffu, mn1, 1));
        mn1 = fmaxf(mn1, __shfl_xor_sync(0xffffffffu, mn1, 2));

        float mN0 = fmaxf(m0, mn0), mN1 = fmaxf(m1, mn1);
        float al0 = __expf(m0 - mN0), al1 = __expf(m1 - mN1);
        m0 = mN0; m1 = mN1;

        float rs0 = 0.f, rs1 = 0.f;
#pragma unroll
        for (int j = 0; j < 8; j++) {
            s[j][0] = __expf(s[j][0] - m0); rs0 += s[j][0];
            s[j][1] = __expf(s[j][1] - m0); rs0 += s[j][1];
            s[j][2] = __expf(s[j][2] - m1); rs1 += s[j][2];
            s[j][3] = __expf(s[j][3] - m1); rs1 += s[j][3];
        }
        rs0 += __shfl_xor_sync(0xffffffffu, rs0, 1);
        rs0 += __shfl_xor_sync(0xffffffffu, rs0, 2);
        rs1 += __shfl_xor_sync(0xffffffffu, rs1, 1);
        rs1 += __shfl_xor_sync(0xffffffffu, rs1, 2);
        l0 = l0 * al0 + rs0;
        l1 = l1 * al1 + rs1;

        // rescale O
#pragma unroll
        for (int j = 0; j < 4; j++) {
            o_[j][0] *= al0; o_[j][1] *= al0;
            o_[j][2] *= al1; o_[j][3] *= al1;
        }

        __syncthreads();   // all warps done reading sKP as K
        // P -> sKP as [t][s] (stride 68), warp-local rows
        {
            const int r0 = w * 16 + lr;
#pragma unroll
            for (int j = 0; j < 8; j++) {
                int c = j * 8 + lc * 2;
                sKP[r0 * 68 + c]           = f2tf(s[j][0]);
                sKP[r0 * 68 + c + 1]       = f2tf(s[j][1]);
                sKP[(r0 + 8) * 68 + c]     = f2tf(s[j][2]);
                sKP[(r0 + 8) * 68 + c + 1] = f2tf(s[j][3]);
            }
        }
        __syncwarp();

        // O += P V : 16 x 32 per warp, 4 n-frags, K=64
#pragma unroll
        for (int ksx = 0; ksx < 8; ksx++) {
            const int ks = ksx * 8;
            uint32_t a[4];
            a[0] = sKP[(w * 16 + lr) * 68 + ks + lc];
            a[1] = sKP[(w * 16 + lr + 8) * 68 + ks + lc];
            a[2] = sKP[(w * 16 + lr) * 68 + ks + 4 + lc];
            a[3] = sKP[(w * 16 + lr + 8) * 68 + ks + 4 + lc];
#pragma unroll
            for (int j = 0; j < 4; j++) {
                uint32_t b0 = sV[(ks + lc) * 40 + j * 8 + lr];
                uint32_t b1 = sV[(ks + 4 + lc) * 40 + j * 8 + lr];
                mma8(o_[j], a, b0, b1);
            }
        }
    }

    // epilogue: ao[n][h*32+dv][t]
    const int n = nh >> 3, h = nh & 7;
    float* __restrict__ aob = g_ao + ((size_t)n * OCH + h * DV) * TT;
    const float inv0 = 1.f / l0, inv1 = 1.f / l1;
    const int tg0 = t0 + w * 16 + lr, tg1 = tg0 + 8;
#pragma unroll
    for (int j = 0; j < 4; j++) {
        int dv = j * 8 + lc * 2;
        aob[(size_t)dv * TT + tg0]       = o_[j][0] * inv0;
        aob[(size_t)(dv + 1) * TT + tg0] = o_[j][1] * inv0;
        aob[(size_t)dv * TT + tg1]       = o_[j][2] * inv1;
        aob[(size_t)(dv + 1) * TT + tg1] = o_[j][3] * inv1;
    }
}

// ---------------------------------------------------------------------------
// Kernel 3: output projection via tf32 mma. Same structure as qkv.
// grid: (T/128, 256/128, NB)
// ---------------------------------------------------------------------------
__global__ __launch_bounds__(256) void out_proj_kernel(
    const float* __restrict__ Wo, const float* __restrict__ bo,
    float* __restrict__ out)
{
    __shared__ uint32_t sA[128 * 36];
    __shared__ uint32_t sB[32 * 136];

    const int n  = blockIdx.z;
    const int o0 = blockIdx.y * 128;
    const int t0 = blockIdx.x * 128;
    const int tid = threadIdx.x;
    const int lane = tid & 31, wid = tid >> 5;
    const int wo = wid >> 1, wt = wid & 1;
    const int lr = lane >> 2, lc = lane & 3;

    const float* __restrict__ xb = g_ao + (size_t)n * OCH * TT;

    float d[2][8][4];
#pragma unroll
    for (int mi = 0; mi < 2; mi++)
#pragma unroll
        for (int j = 0; j < 8; j++)
#pragma unroll
            for (int q = 0; q < 4; q++) d[mi][j][q] = 0.f;

    for (int k0 = 0; k0 < OCH; k0 += 32) {
        __syncthreads();
#pragma unroll
        for (int u = 0; u < 4; u++) {
            int idx = tid + u * 256;
            int o = idx >> 3, kq = idx & 7;
            float4 w = *(const float4*)(Wo + (size_t)(o0 + o) * OCH + k0 + kq * 4);
            uint32_t* p = &sA[o * 36 + kq * 4];
            p[0] = f2tf(w.x); p[1] = f2tf(w.y); p[2] = f2tf(w.z); p[3] = f2tf(w.w);
        }
#pragma unroll
        for (int u = 0; u < 4; u++) {
            int idx = tid + u * 256;
            int k = idx >> 5, tq = idx & 31;
            float4 v = *(const float4*)(xb + (size_t)(k0 + k) * TT + t0 + tq * 4);
            uint32_t* p = &sB[k * 136 + tq * 4];
            p[0] = f2tf(v.x); p[1] = f2tf(v.y); p[2] = f2tf(v.z); p[3] = f2tf(v.w);
        }
        __syncthreads();

#pragma unroll
        for (int kk = 0; kk < 4; kk++) {
            const int kc = kk * 8;
            uint32_t a[2][4];
#pragma unroll
            for (int mi = 0; mi < 2; mi++) {
                int row = wo * 32 + mi * 16 + lr;
                a[mi][0] = sA[row * 36 + kc + lc];
                a[mi][1] = sA[(row + 8) * 36 + kc + lc];
                a[mi][2] = sA[row * 36 + kc + 4 + lc];
                a[mi][3] = sA[(row + 8) * 36 + kc + 4 + lc];
            }
#pragma unroll
            for (int j = 0; j < 8; j++) {
                int col = wt * 64 + j * 8 + lr;
                uint32_t b0 = sB[(kc + lc) * 136 + col];
                uint32_t b1 = sB[(kc + 4 + lc) * 136 + col];
                mma8(d[0][j], a[0], b0, b1);
                mma8(d[1][j], a[1], b0, b1);
            }
        }
    }

#pragma unroll
    for (int mi = 0; mi < 2; mi++) {
#pragma unroll
        for (int half = 0; half < 2; half++) {
            int o = o0 + wo * 32 + mi * 16 + half * 8 + lr;
            float bias = bo[o];
            float* dst = out + ((size_t)n * OCH + o) * TT;
#pragma unroll
            for (int j = 0; j < 8; j++) {
                int t = t0 + wt * 64 + j * 8 + lc * 2;
                dst[t]     = d[mi][j][half * 2 + 0] + bias;
                dst[t + 1] = d[mi][j][half * 2 + 1] + bias;
            }
        }
    }
}

// ---------------------------------------------------------------------------
extern "C" void kernel_launch(void* const* d_in, const int* in_sizes, int n_in,
                              void* d_out, int out_size)
{
    const float* x   = (const float*)d_in[0];
    const float* Wq  = (const float*)d_in[1];
    const float* bq  = (const float*)d_in[2];
    const float* Wkv = (const float*)d_in[3];
    const float* bkv = (const float*)d_in[4];
    const float* Wo  = (const float*)d_in[5];
    const float* bo  = (const float*)d_in[6];
    float* out = (float*)d_out;

    qkv_kernel<<<dim3(TT / 128, 1280 / 128, NB), 256>>>(x, Wq, bq, Wkv, bkv);
    attn_kernel<<<dim3(TT / 64, NB * HDS), 128>>>();
    out_proj_kernel<<<dim3(TT / 128, OCH / 128, NB), 256>>>(Wo, bo, out);
}

// round 8
// speedup vs baseline: 3.8891x; 1.3231x over previous
#include <cuda_runtime.h>
#include <cstdint>

#define NB   8
#define CIN  256
#define TT   1024
#define HDS  8
#define DQK  64
#define DV   32
#define OCH  256

// Scratch (allocation-free rule: __device__ globals)
__device__ float g_q[NB * HDS * DQK * TT];   // [n][h][d][t], tf32-rounded
__device__ float g_k[NB * HDS * DQK * TT];   // [n][h][d][t], tf32-rounded
__device__ float g_v[NB * HDS * DV  * TT];   // [n][h][dv][t], tf32-rounded
__device__ float g_ao[NB * OCH * TT];        // [n][c=h*32+dv][t], tf32-rounded

// ---------------------------------------------------------------------------
// tf32 helpers
// ---------------------------------------------------------------------------
__device__ __forceinline__ uint32_t f2tf(float f) {
    uint32_t u;
    asm("cvt.rna.tf32.f32 %0, %1;" : "=r"(u) : "f"(f));
    return u;
}
__device__ __forceinline__ float f2tf_f(float f) {
    return __uint_as_float(f2tf(f));
}

// D(16x8) += A(16x8,row) * B(8x8,col), tf32 in, f32 accum
__device__ __forceinline__ void mma8(float* d, const uint32_t* a,
                                     uint32_t b0, uint32_t b1) {
    asm volatile(
        "mma.sync.aligned.m16n8k8.row.col.f32.tf32.tf32.f32 "
        "{%0,%1,%2,%3}, {%4,%5,%6,%7}, {%8,%9}, {%0,%1,%2,%3};\n"
        : "+f"(d[0]), "+f"(d[1]), "+f"(d[2]), "+f"(d[3])
        : "r"(a[0]), "r"(a[1]), "r"(a[2]), "r"(a[3]), "r"(b0), "r"(b1));
}

__device__ __forceinline__ uint32_t s2u(const void* p) {
    return (uint32_t)__cvta_generic_to_shared(p);
}
__device__ __forceinline__ void cpa16(uint32_t dst, const void* src) {
    asm volatile("cp.async.cg.shared.global [%0], [%1], 16;\n"
                 :: "r"(dst), "l"(src));
}
__device__ __forceinline__ void cpa_commit() {
    asm volatile("cp.async.commit_group;\n");
}
__device__ __forceinline__ void cpa_wait0() {
    asm volatile("cp.async.wait_group 0;\n");
}

// ---------------------------------------------------------------------------
// Kernel 1: fused QKV projection via tf32 mma. 128o x 128t tile, K=256.
// grid: (T/128, 1280/128, NB). Outputs tf32-rounded.
// ---------------------------------------------------------------------------
__global__ __launch_bounds__(256) void qkv_kernel(
    const float* __restrict__ x, const float* __restrict__ Wq,
    const float* __restrict__ bq, const float* __restrict__ Wkv,
    const float* __restrict__ bkv)
{
    __shared__ uint32_t sA[128 * 36];
    __shared__ uint32_t sB[32 * 136];

    const int n  = blockIdx.z;
    const int o0 = blockIdx.y * 128;
    const int t0 = blockIdx.x * 128;
    const int tid = threadIdx.x;
    const int lane = tid & 31, wid = tid >> 5;
    const int wo = wid >> 1, wt = wid & 1;
    const int lr = lane >> 2, lc = lane & 3;

    const float* __restrict__ xb = x + (size_t)n * CIN * TT;

    float d[2][8][4];
#pragma unroll
    for (int mi = 0; mi < 2; mi++)
#pragma unroll
        for (int j = 0; j < 8; j++)
#pragma unroll
            for (int q = 0; q < 4; q++) d[mi][j][q] = 0.f;

    for (int k0 = 0; k0 < CIN; k0 += 32) {
        __syncthreads();
#pragma unroll
        for (int u = 0; u < 4; u++) {
            int idx = tid + u * 256;
            int o = idx >> 3, kq = idx & 7;
            int go = o0 + o;
            const float* src = (go < 512)
                ? (Wq  + (size_t)go * CIN + k0 + kq * 4)
                : (Wkv + (size_t)(go - 512) * CIN + k0 + kq * 4);
            float4 w = *(const float4*)src;
            uint32_t* p = &sA[o * 36 + kq * 4];
            p[0] = f2tf(w.x); p[1] = f2tf(w.y); p[2] = f2tf(w.z); p[3] = f2tf(w.w);
        }
#pragma unroll
        for (int u = 0; u < 4; u++) {
            int idx = tid + u * 256;
            int k = idx >> 5, tq = idx & 31;
            float4 v = *(const float4*)(xb + (size_t)(k0 + k) * TT + t0 + tq * 4);
            uint32_t* p = &sB[k * 136 + tq * 4];
            p[0] = f2tf(v.x); p[1] = f2tf(v.y); p[2] = f2tf(v.z); p[3] = f2tf(v.w);
        }
        __syncthreads();

#pragma unroll
        for (int kk = 0; kk < 4; kk++) {
            const int kc = kk * 8;
            uint32_t a[2][4];
#pragma unroll
            for (int mi = 0; mi < 2; mi++) {
                int row = wo * 32 + mi * 16 + lr;
                a[mi][0] = sA[row * 36 + kc + lc];
                a[mi][1] = sA[(row + 8) * 36 + kc + lc];
                a[mi][2] = sA[row * 36 + kc + 4 + lc];
                a[mi][3] = sA[(row + 8) * 36 + kc + 4 + lc];
            }
#pragma unroll
            for (int j = 0; j < 8; j++) {
                int col = wt * 64 + j * 8 + lr;
                uint32_t b0 = sB[(kc + lc) * 136 + col];
                uint32_t b1 = sB[(kc + 4 + lc) * 136 + col];
                mma8(d[0][j], a[0], b0, b1);
                mma8(d[1][j], a[1], b0, b1);
            }
        }
    }

    // epilogue: route rows to g_q / g_k / g_v, tf32-rounded
#pragma unroll
    for (int mi = 0; mi < 2; mi++) {
#pragma unroll
        for (int half = 0; half < 2; half++) {
            int o = o0 + wo * 32 + mi * 16 + half * 8 + lr;
            float bias;
            float* dst;
            if (o < 512) {
                int h = o >> 6, dd = o & 63;
                bias = bq[o];
                dst = g_q + (((size_t)n * HDS + h) * DQK + dd) * TT;
            } else if (o < 1024) {
                int oo = o - 512, h = oo >> 6, dd = oo & 63;
                bias = bkv[o - 512];
                dst = g_k + (((size_t)n * HDS + h) * DQK + dd) * TT;
            } else {
                int oo = o - 1024, h = oo >> 5, dd = oo & 31;
                bias = bkv[o - 512];
                dst = g_v + (((size_t)n * HDS + h) * DV + dd) * TT;
            }
#pragma unroll
            for (int j = 0; j < 8; j++) {
                int t = t0 + wt * 64 + j * 8 + lc * 2;
                dst[t]     = f2tf_f(d[mi][j][half * 2 + 0] + bias);
                dst[t + 1] = f2tf_f(d[mi][j][half * 2 + 1] + bias);
            }
        }
    }
}

// ---------------------------------------------------------------------------
// Kernel 2: flash attention, q-tile 128, 8 warps (warp-local 16 q-rows),
// s-tile 64, double-buffered K/V via cp.async, Q fragments in registers.
// dyn smem: sK[2][64*72] | sV[2][32*68] | sP[128*68]  = 89088 B
// sV layout is [dv][s] (direct cp.async copy of g_v rows).
// grid: (8, NB*HDS), block 256.
// ---------------------------------------------------------------------------
#define SK_STRIDE 72
#define SV_STRIDE 68
#define SP_STRIDE 68
#define SK_BUF (64 * SK_STRIDE)
#define SV_BUF (32 * SV_STRIDE)
#define ATTN_SMEM_WORDS (2 * SK_BUF + 2 * SV_BUF + 128 * SP_STRIDE)

__global__ __launch_bounds__(256, 2) void attn_kernel()
{
    extern __shared__ uint32_t dynsmem[];
    uint32_t* sK = dynsmem;                   // 2 x [d=64][s=64] stride 72
    uint32_t* sV = dynsmem + 2 * SK_BUF;      // 2 x [dv=32][s=64] stride 68
    uint32_t* sP = sV + 2 * SV_BUF;           // [t=128][s=64] stride 68

    const int nh = blockIdx.y;
    const int qb = (gridDim.x - 1) - blockIdx.x;   // big causal blocks first
    const int tid = threadIdx.x;
    const int lane = tid & 31, w = tid >> 5;
    const int lr = lane >> 2, lc = lane & 3;
    const float scale = 0.125f;

    const float* __restrict__ qp = g_q + (size_t)nh * DQK * TT;
    const float* __restrict__ kp = g_k + (size_t)nh * DQK * TT;
    const float* __restrict__ vp = g_v + (size_t)nh * DV * TT;

    const int t0 = qb * 128;
    const int t0w = t0 + w * 16;              // warp's first q row
    const int nkb = 2 * qb + 2;

    // Q fragments in registers: qfr[kd][0..3], values pre-rounded to tf32
    const uint32_t* __restrict__ qpu = (const uint32_t*)qp;
    uint32_t qfr[8][4];
#pragma unroll
    for (int kd = 0; kd < 8; kd++) {
        int d0 = kd * 8 + lc;
        qfr[kd][0] = qpu[(size_t)d0 * TT + t0w + lr];
        qfr[kd][1] = qpu[(size_t)d0 * TT + t0w + lr + 8];
        qfr[kd][2] = qpu[(size_t)(d0 + 4) * TT + t0w + lr];
        qfr[kd][3] = qpu[(size_t)(d0 + 4) * TT + t0w + lr + 8];
    }

    // prologue: issue K/V tile 0
    {
        const int s0 = 0;
#pragma unroll
        for (int u = 0; u < 4; u++) {
            int idx = tid + u * 256;
            int dd = idx >> 4, sg = idx & 15;
            cpa16(s2u(&sK[dd * SK_STRIDE + sg * 4]), kp + (size_t)dd * TT + s0 + sg * 4);
        }
#pragma unroll
        for (int u = 0; u < 2; u++) {
            int idx = tid + u * 256;
            int dd = idx >> 4, sg = idx & 15;
            cpa16(s2u(&sV[dd * SV_STRIDE + sg * 4]), vp + (size_t)dd * TT + s0 + sg * 4);
        }
        cpa_commit();
    }

    float m0 = -1e30f, m1 = -1e30f, l0 = 0.f, l1 = 0.f;
    float o_[4][4];
#pragma unroll
    for (int j = 0; j < 4; j++)
#pragma unroll
        for (int q = 0; q < 4; q++) o_[j][q] = 0.f;

    for (int kb = 0; kb < nkb; kb++) {
        cpa_wait0();
        __syncthreads();

        // prefetch next tile into the other buffer
        if (kb + 1 < nkb) {
            const int sn = (kb + 1) * 64;
            uint32_t* sKn = sK + ((kb + 1) & 1) * SK_BUF;
            uint32_t* sVn = sV + ((kb + 1) & 1) * SV_BUF;
#pragma unroll
            for (int u = 0; u < 4; u++) {
                int idx = tid + u * 256;
                int dd = idx >> 4, sg = idx & 15;
                cpa16(s2u(&sKn[dd * SK_STRIDE + sg * 4]), kp + (size_t)dd * TT + sn + sg * 4);
            }
#pragma unroll
            for (int u = 0; u < 2; u++) {
                int idx = tid + u * 256;
                int dd = idx >> 4, sg = idx & 15;
                cpa16(s2u(&sVn[dd * SV_STRIDE + sg * 4]), vp + (size_t)dd * TT + sn + sg * 4);
            }
            cpa_commit();
        }

        const int s0 = kb * 64;
        const bool active = (s0 <= t0w + 15);
        if (active) {
            const uint32_t* sKb = sK + (kb & 1) * SK_BUF;
            const uint32_t* sVb = sV + (kb & 1) * SV_BUF;

            // S = Q K^T : 16 x 64 per warp
            float s[8][4];
#pragma unroll
            for (int j = 0; j < 8; j++)
#pragma unroll
                for (int q = 0; q < 4; q++) s[j][q] = 0.f;

#pragma unroll
            for (int kd = 0; kd < 8; kd++) {
                const int kc = kd * 8;
#pragma unroll
                for (int j = 0; j < 8; j++) {
                    uint32_t b0 = sKb[(kc + lc) * SK_STRIDE + j * 8 + lr];
                    uint32_t b1 = sKb[(kc + 4 + lc) * SK_STRIDE + j * 8 + lr];
                    mma8(s[j], qfr[kd], b0, b1);
                }
            }

            // scale + causal mask
            const int tg0 = t0w + lr, tg1 = tg0 + 8;
            const bool need_mask = (s0 + 63 > t0w);
#pragma unroll
            for (int j = 0; j < 8; j++) {
                int sg = s0 + j * 8 + lc * 2;
                s[j][0] *= scale; s[j][1] *= scale; s[j][2] *= scale; s[j][3] *= scale;
                if (need_mask) {
                    if (sg     > tg0) s[j][0] = -1e30f;
                    if (sg + 1 > tg0) s[j][1] = -1e30f;
                    if (sg     > tg1) s[j][2] = -1e30f;
                    if (sg + 1 > tg1) s[j][3] = -1e30f;
                }
            }

            // online softmax
            float mn0 = -1e30f, mn1 = -1e30f;
#pragma unroll
            for (int j = 0; j < 8; j++) {
                mn0 = fmaxf(mn0, fmaxf(s[j][0], s[j][1]));
                mn1 = fmaxf(mn1, fmaxf(s[j][2], s[j][3]));
            }
            mn0 = fmaxf(mn0, __shfl_xor_sync(0xffffffffu, mn0, 1));
            mn0 = fmaxf(mn0, __shfl_xor_sync(0xffffffffu, mn0, 2));
            mn1 = fmaxf(mn1, __shfl_xor_sync(0xffffffffu, mn1, 1));
            mn1 = fmaxf(mn1, __shfl_xor_sync(0xffffffffu, mn1, 2));

            float mN0 = fmaxf(m0, mn0), mN1 = fmaxf(m1, mn1);
            float al0 = __expf(m0 - mN0), al1 = __expf(m1 - mN1);
            m0 = mN0; m1 = mN1;

            float rs0 = 0.f, rs1 = 0.f;
#pragma unroll
            for (int j = 0; j < 8; j++) {
                s[j][0] = __expf(s[j][0] - m0); rs0 += s[j][0];
                s[j][1] = __expf(s[j][1] - m0); rs0 += s[j][1];
                s[j][2] = __expf(s[j][2] - m1); rs1 += s[j][2];
                s[j][3] = __expf(s[j][3] - m1); rs1 += s[j][3];
            }
            rs0 += __shfl_xor_sync(0xffffffffu, rs0, 1);
            rs0 += __shfl_xor_sync(0xffffffffu, rs0, 2);
            rs1 += __shfl_xor_sync(0xffffffffu, rs1, 1);
            rs1 += __shfl_xor_sync(0xffffffffu, rs1, 2);
            l0 = l0 * al0 + rs0;
            l1 = l1 * al1 + rs1;

#pragma unroll
            for (int j = 0; j < 4; j++) {
                o_[j][0] *= al0; o_[j][1] *= al0;
                o_[j][2] *= al1; o_[j][3] *= al1;
            }

            // P -> sP rows of this warp (warp-local, no block barrier)
            {
                const int r0 = w * 16 + lr;
#pragma unroll
                for (int j = 0; j < 8; j++) {
                    int c = j * 8 + lc * 2;
                    sP[r0 * SP_STRIDE + c]           = f2tf(s[j][0]);
                    sP[r0 * SP_STRIDE + c + 1]       = f2tf(s[j][1]);
                    sP[(r0 + 8) * SP_STRIDE + c]     = f2tf(s[j][2]);
                    sP[(r0 + 8) * SP_STRIDE + c + 1] = f2tf(s[j][3]);
                }
            }
            __syncwarp();

            // O += P V : 16 x 32 per warp.  sVb is [dv][s]:
            // B element (k=s, n=dv) lives at sVb[dv*SV_STRIDE + s].
#pragma unroll
            for (int ksx = 0; ksx < 8; ksx++) {
                const int ks = ksx * 8;
                uint32_t a[4];
                a[0] = sP[(w * 16 + lr) * SP_STRIDE + ks + lc];
                a[1] = sP[(w * 16 + lr + 8) * SP_STRIDE + ks + lc];
                a[2] = sP[(w * 16 + lr) * SP_STRIDE + ks + 4 + lc];
                a[3] = sP[(w * 16 + lr + 8) * SP_STRIDE + ks + 4 + lc];
#pragma unroll
                for (int j = 0; j < 4; j++) {
                    uint32_t b0 = sVb[(j * 8 + lr) * SV_STRIDE + ks + lc];
                    uint32_t b1 = sVb[(j * 8 + lr) * SV_STRIDE + ks + 4 + lc];
                    mma8(o_[j], a, b0, b1);
                }
            }
        }
    }

    // epilogue: ao[n][h*32+dv][t], tf32-rounded
    const int n = nh >> 3, h = nh & 7;
    float* __restrict__ aob = g_ao + ((size_t)n * OCH + h * DV) * TT;
    const float inv0 = 1.f / l0, inv1 = 1.f / l1;
    const int tg0 = t0w + lr, tg1 = tg0 + 8;
#pragma unroll
    for (int j = 0; j < 4; j++) {
        int dv = j * 8 + lc * 2;
        aob[(size_t)dv * TT + tg0]       = f2tf_f(o_[j][0] * inv0);
        aob[(size_t)(dv + 1) * TT + tg0] = f2tf_f(o_[j][1] * inv0);
        aob[(size_t)dv * TT + tg1]       = f2tf_f(o_[j][2] * inv1);
        aob[(size_t)(dv + 1) * TT + tg1] = f2tf_f(o_[j][3] * inv1);
    }
}

// ---------------------------------------------------------------------------
// Kernel 3: output projection via tf32 mma. grid: (T/128, 256/128, NB)
// ---------------------------------------------------------------------------
__global__ __launch_bounds__(256) void out_proj_kernel(
    const float* __restrict__ Wo, const float* __restrict__ bo,
    float* __restrict__ out)
{
    __shared__ uint32_t sA[128 * 36];
    __shared__ uint32_t sB[32 * 136];

    const int n  = blockIdx.z;
    const int o0 = blockIdx.y * 128;
    const int t0 = blockIdx.x * 128;
    const int tid = threadIdx.x;
    const int lane = tid & 31, wid = tid >> 5;
    const int wo = wid >> 1, wt = wid & 1;
    const int lr = lane >> 2, lc = lane & 3;

    const float* __restrict__ xb = g_ao + (size_t)n * OCH * TT;

    float d[2][8][4];
#pragma unroll
    for (int mi = 0; mi < 2; mi++)
#pragma unroll
        for (int j = 0; j < 8; j++)
#pragma unroll
            for (int q = 0; q < 4; q++) d[mi][j][q] = 0.f;

    for (int k0 = 0; k0 < OCH; k0 += 32) {
        __syncthreads();
#pragma unroll
        for (int u = 0; u < 4; u++) {
            int idx = tid + u * 256;
            int o = idx >> 3, kq = idx & 7;
            float4 w = *(const float4*)(Wo + (size_t)(o0 + o) * OCH + k0 + kq * 4);
            uint32_t* p = &sA[o * 36 + kq * 4];
            p[0] = f2tf(w.x); p[1] = f2tf(w.y); p[2] = f2tf(w.z); p[3] = f2tf(w.w);
        }
#pragma unroll
        for (int u = 0; u < 4; u++) {
            int idx = tid + u * 256;
            int k = idx >> 5, tq = idx & 31;
            // g_ao is already tf32-rounded: raw copy
            float4 v = *(const float4*)(xb + (size_t)(k0 + k) * TT + t0 + tq * 4);
            uint32_t* p = &sB[k * 136 + tq * 4];
            p[0] = __float_as_uint(v.x); p[1] = __float_as_uint(v.y);
            p[2] = __float_as_uint(v.z); p[3] = __float_as_uint(v.w);
        }
        __syncthreads();

#pragma unroll
        for (int kk = 0; kk < 4; kk++) {
            const int kc = kk * 8;
            uint32_t a[2][4];
#pragma unroll
            for (int mi = 0; mi < 2; mi++) {
                int row = wo * 32 + mi * 16 + lr;
                a[mi][0] = sA[row * 36 + kc + lc];
                a[mi][1] = sA[(row + 8) * 36 + kc + lc];
                a[mi][2] = sA[row * 36 + kc + 4 + lc];
                a[mi][3] = sA[(row + 8) * 36 + kc + 4 + lc];
            }
#pragma unroll
            for (int j = 0; j < 8; j++) {
                int col = wt * 64 + j * 8 + lr;
                uint32_t b0 = sB[(kc + lc) * 136 + col];
                uint32_t b1 = sB[(kc + 4 + lc) * 136 + col];
                mma8(d[0][j], a[0], b0, b1);
                mma8(d[1][j], a[1], b0, b1);
            }
        }
    }

#pragma unroll
    for (int mi = 0; mi < 2; mi++) {
#pragma unroll
        for (int half = 0; half < 2; half++) {
            int o = o0 + wo * 32 + mi * 16 + half * 8 + lr;
            float bias = bo[o];
            float* dst = out + ((size_t)n * OCH + o) * TT;
#pragma unroll
            for (int j = 0; j < 8; j++) {
                int t = t0 + wt * 64 + j * 8 + lc * 2;
                dst[t]     = d[mi][j][half * 2 + 0] + bias;
                dst[t + 1] = d[mi][j][half * 2 + 1] + bias;
            }
        }
    }
}

// ---------------------------------------------------------------------------
extern "C" void kernel_launch(void* const* d_in, const int* in_sizes, int n_in,
                              void* d_out, int out_size)
{
    const float* x   = (const float*)d_in[0];
    const float* Wq  = (const float*)d_in[1];
    const float* bq  = (const float*)d_in[2];
    const float* Wkv = (const float*)d_in[3];
    const float* bkv = (const float*)d_in[4];
    const float* Wo  = (const float*)d_in[5];
    const float* bo  = (const float*)d_in[6];
    float* out = (float*)d_out;

    cudaFuncSetAttribute(attn_kernel,
                         cudaFuncAttributeMaxDynamicSharedMemorySize,
                         ATTN_SMEM_WORDS * 4);

    qkv_kernel<<<dim3(TT / 128, 1280 / 128, NB), 256>>>(x, Wq, bq, Wkv, bkv);
    attn_kernel<<<dim3(TT / 128, NB * HDS), 256, ATTN_SMEM_WORDS * 4>>>();
    out_proj_kernel<<<dim3(TT / 128, OCH / 128, NB), 256>>>(Wo, bo, out);
}

// round 13
// speedup vs baseline: 4.0466x; 1.0405x over previous
#include <cuda_runtime.h>
#include <cstdint>

#define NB   8
#define CIN  256
#define TT   1024
#define HDS  8
#define DQK  64
#define DV   32
#define OCH  256

// Scratch (allocation-free rule: __device__ globals)
__device__ float g_q[NB * HDS * DQK * TT];   // [n][h][d][t], tf32-rounded
__device__ float g_k[NB * HDS * DQK * TT];   // [n][h][d][t], tf32-rounded
__device__ float g_v[NB * HDS * DV  * TT];   // [n][h][dv][t], tf32-rounded
__device__ float g_ao[NB * OCH * TT];        // [n][c=h*32+dv][t], tf32-rounded
__device__ float g_x[NB * CIN * TT];         // tf32-rounded input
__device__ float g_w[1280 * CIN];            // tf32-rounded [Wq;Wkv]
__device__ float g_wo[OCH * OCH];            // tf32-rounded Wo

// ---------------------------------------------------------------------------
// tf32 helpers
// ---------------------------------------------------------------------------
__device__ __forceinline__ uint32_t f2tf(float f) {
    uint32_t u;
    asm("cvt.rna.tf32.f32 %0, %1;" : "=r"(u) : "f"(f));
    return u;
}
__device__ __forceinline__ float f2tf_f(float f) {
    return __uint_as_float(f2tf(f));
}

// D(16x8) += A(16x8,row) * B(8x8,col), tf32 in, f32 accum
__device__ __forceinline__ void mma8(float* d, const uint32_t* a,
                                     uint32_t b0, uint32_t b1) {
    asm volatile(
        "mma.sync.aligned.m16n8k8.row.col.f32.tf32.tf32.f32 "
        "{%0,%1,%2,%3}, {%4,%5,%6,%7}, {%8,%9}, {%0,%1,%2,%3};\n"
        : "+f"(d[0]), "+f"(d[1]), "+f"(d[2]), "+f"(d[3])
        : "r"(a[0]), "r"(a[1]), "r"(a[2]), "r"(a[3]), "r"(b0), "r"(b1));
}

__device__ __forceinline__ uint32_t s2u(const void* p) {
    return (uint32_t)__cvta_generic_to_shared(p);
}
__device__ __forceinline__ void cpa16(uint32_t dst, const void* src) {
    asm volatile("cp.async.cg.shared.global [%0], [%1], 16;\n"
                 :: "r"(dst), "l"(src));
}
__device__ __forceinline__ void cpa_commit() {
    asm volatile("cp.async.commit_group;\n");
}
__device__ __forceinline__ void cpa_wait0() {
    asm volatile("cp.async.wait_group 0;\n");
}
__device__ __forceinline__ void cpa_wait1() {
    asm volatile("cp.async.wait_group 1;\n");
}

// ---------------------------------------------------------------------------
// Kernel 0: tf32 pre-rounding pass (x, [Wq;Wkv], Wo), float4 grid-stride.
// ---------------------------------------------------------------------------
#define NX4 (NB * CIN * TT / 4)       // 524288
#define NW4 (1280 * CIN / 4)          // 81920
#define NWO4 (OCH * OCH / 4)          // 16384
__global__ __launch_bounds__(256) void round_pre_kernel(
    const float* __restrict__ x, const float* __restrict__ Wq,
    const float* __restrict__ Wkv, const float* __restrict__ Wo)
{
    const int total = NX4 + NW4 + NWO4;
    for (int i = blockIdx.x * blockDim.x + threadIdx.x; i < total;
         i += gridDim.x * blockDim.x) {
        float4 v; float4* dst;
        if (i < NX4) {
            v = ((const float4*)x)[i];
            dst = (float4*)g_x + i;
        } else if (i < NX4 + NW4) {
            int j = i - NX4;
            const int wq4 = 512 * CIN / 4;
            v = (j < wq4) ? ((const float4*)Wq)[j] : ((const float4*)Wkv)[j - wq4];
            dst = (float4*)g_w + j;
        } else {
            int j = i - NX4 - NW4;
            v = ((const float4*)Wo)[j];
            dst = (float4*)g_wo + j;
        }
        float4 r;
        r.x = f2tf_f(v.x); r.y = f2tf_f(v.y); r.z = f2tf_f(v.z); r.w = f2tf_f(v.w);
        *dst = r;
    }
}

// ---------------------------------------------------------------------------
// Kernel 1: fused QKV projection via tf32 mma, cp.async double-buffered.
// 128o x 128t tile, K=256 in 8 stages of 32.
// dyn smem: 2 x (sA[128*36] + sB[32*136]) = 71680 B
// grid: (T/128, 1280/128, NB). Outputs tf32-rounded.
// ---------------------------------------------------------------------------
#define GA_W 36
#define GB_W 136
#define GA_BUF (128 * GA_W)
#define GB_BUF (32 * GB_W)
#define GSTAGE (GA_BUF + GB_BUF)
#define GEMM_SMEM_BYTES (2 * GSTAGE * 4)

__device__ __forceinline__ void gemm_fill_stage(
    uint32_t* sA, uint32_t* sB, const float* __restrict__ wsrc,
    const float* __restrict__ xsrc, int k0, int tid)
{
#pragma unroll
    for (int u = 0; u < 4; u++) {
        int idx = tid + u * 256;              // 1024: o(128) x kq(8)
        int o = idx >> 3, kq = idx & 7;
        cpa16(s2u(&sA[o * GA_W + kq * 4]), wsrc + (size_t)o * CIN + k0 + kq * 4);
    }
#pragma unroll
    for (int u = 0; u < 4; u++) {
        int idx = tid + u * 256;              // 1024: k(32) x tq(32)
        int k = idx >> 5, tq = idx & 31;
        cpa16(s2u(&sB[k * GB_W + tq * 4]), xsrc + (size_t)(k0 + k) * TT + tq * 4);
    }
    cpa_commit();
}

__global__ __launch_bounds__(256, 2) void qkv_kernel(
    const float* __restrict__ bq, const float* __restrict__ bkv)
{
    extern __shared__ uint32_t gsm[];
    const int n  = blockIdx.z;
    const int o0 = blockIdx.y * 128;
    const int t0 = blockIdx.x * 128;
    const int tid = threadIdx.x;
    const int lane = tid & 31, wid = tid >> 5;
    const int wo = wid >> 1, wt = wid & 1;
    const int lr = lane >> 2, lc = lane & 3;

    const float* __restrict__ wsrc = g_w + (size_t)o0 * CIN;
    const float* __restrict__ xsrc = g_x + (size_t)n * CIN * TT + t0;

    float d[2][8][4];
#pragma unroll
    for (int mi = 0; mi < 2; mi++)
#pragma unroll
        for (int j = 0; j < 8; j++)
#pragma unroll
            for (int q = 0; q < 4; q++) d[mi][j][q] = 0.f;

    gemm_fill_stage(gsm, gsm + GA_BUF, wsrc, xsrc, 0, tid);

#pragma unroll
    for (int st = 0; st < 8; st++) {
        uint32_t* sA = gsm + (st & 1) * GSTAGE;
        uint32_t* sB = sA + GA_BUF;
        if (st + 1 < 8) {
            uint32_t* nA = gsm + ((st + 1) & 1) * GSTAGE;
            gemm_fill_stage(nA, nA + GA_BUF, wsrc, xsrc, (st + 1) * 32, tid);
            cpa_wait1();
        } else {
            cpa_wait0();
        }
        __syncthreads();

#pragma unroll
        for (int kk = 0; kk < 4; kk++) {
            const int kc = kk * 8;
            uint32_t a[2][4];
#pragma unroll
            for (int mi = 0; mi < 2; mi++) {
                int row = wo * 32 + mi * 16 + lr;
                a[mi][0] = sA[row * GA_W + kc + lc];
                a[mi][1] = sA[(row + 8) * GA_W + kc + lc];
                a[mi][2] = sA[row * GA_W + kc + 4 + lc];
                a[mi][3] = sA[(row + 8) * GA_W + kc + 4 + lc];
            }
#pragma unroll
            for (int j = 0; j < 8; j++) {
                int col = wt * 64 + j * 8 + lr;
                uint32_t b0 = sB[(kc + lc) * GB_W + col];
                uint32_t b1 = sB[(kc + 4 + lc) * GB_W + col];
                mma8(d[0][j], a[0], b0, b1);
                mma8(d[1][j], a[1], b0, b1);
            }
        }
        __syncthreads();
    }

    // epilogue: route rows to g_q / g_k / g_v, tf32-rounded
#pragma unroll
    for (int mi = 0; mi < 2; mi++) {
#pragma unroll
        for (int half = 0; half < 2; half++) {
            int o = o0 + wo * 32 + mi * 16 + half * 8 + lr;
            float bias;
            float* dst;
            if (o < 512) {
                int h = o >> 6, dd = o & 63;
                bias = bq[o];
                dst = g_q + (((size_t)n * HDS + h) * DQK + dd) * TT;
            } else if (o < 1024) {
                int oo = o - 512, h = oo >> 6, dd = oo & 63;
                bias = bkv[o - 512];
                dst = g_k + (((size_t)n * HDS + h) * DQK + dd) * TT;
            } else {
                int oo = o - 1024, h = oo >> 5, dd = oo & 31;
                bias = bkv[o - 512];
                dst = g_v + (((size_t)n * HDS + h) * DV + dd) * TT;
            }
#pragma unroll
            for (int j = 0; j < 8; j++) {
                int t = t0 + wt * 64 + j * 8 + lc * 2;
                dst[t]     = f2tf_f(d[mi][j][half * 2 + 0] + bias);
                dst[t + 1] = f2tf_f(d[mi][j][half * 2 + 1] + bias);
            }
        }
    }
}

// ---------------------------------------------------------------------------
// Kernel 2: flash attention (unchanged from R8 pass).
// ---------------------------------------------------------------------------
#define SK_STRIDE 72
#define SV_STRIDE 68
#define SP_STRIDE 68
#define SK_BUF (64 * SK_STRIDE)
#define SV_BUF (32 * SV_STRIDE)
#define ATTN_SMEM_WORDS (2 * SK_BUF + 2 * SV_BUF + 128 * SP_STRIDE)

__global__ __launch_bounds__(256, 2) void attn_kernel()
{
    extern __shared__ uint32_t dynsmem[];
    uint32_t* sK = dynsmem;                   // 2 x [d=64][s=64] stride 72
    uint32_t* sV = dynsmem + 2 * SK_BUF;      // 2 x [dv=32][s=64] stride 68
    uint32_t* sP = sV + 2 * SV_BUF;           // [t=128][s=64] stride 68

    const int nh = blockIdx.y;
    const int qb = (gridDim.x - 1) - blockIdx.x;
    const int tid = threadIdx.x;
    const int lane = tid & 31, w = tid >> 5;
    const int lr = lane >> 2, lc = lane & 3;
    const float scale = 0.125f;

    const float* __restrict__ qp = g_q + (size_t)nh * DQK * TT;
    const float* __restrict__ kp = g_k + (size_t)nh * DQK * TT;
    const float* __restrict__ vp = g_v + (size_t)nh * DV * TT;

    const int t0 = qb * 128;
    const int t0w = t0 + w * 16;
    const int nkb = 2 * qb + 2;

    const uint32_t* __restrict__ qpu = (const uint32_t*)qp;
    uint32_t qfr[8][4];
#pragma unroll
    for (int kd = 0; kd < 8; kd++) {
        int d0 = kd * 8 + lc;
        qfr[kd][0] = qpu[(size_t)d0 * TT + t0w + lr];
        qfr[kd][1] = qpu[(size_t)d0 * TT + t0w + lr + 8];
        qfr[kd][2] = qpu[(size_t)(d0 + 4) * TT + t0w + lr];
        qfr[kd][3] = qpu[(size_t)(d0 + 4) * TT + t0w + lr + 8];
    }

    {
        const int s0 = 0;
#pragma unroll
        for (int u = 0; u < 4; u++) {
            int idx = tid + u * 256;
            int dd = idx >> 4, sg = idx & 15;
            cpa16(s2u(&sK[dd * SK_STRIDE + sg * 4]), kp + (size_t)dd * TT + s0 + sg * 4);
        }
#pragma unroll
        for (int u = 0; u < 2; u++) {
            int idx = tid + u * 256;
            int dd = idx >> 4, sg = idx & 15;
            cpa16(s2u(&sV[dd * SV_STRIDE + sg * 4]), vp + (size_t)dd * TT + s0 + sg * 4);
        }
        cpa_commit();
    }

    float m0 = -1e30f, m1 = -1e30f, l0 = 0.f, l1 = 0.f;
    float o_[4][4];
#pragma unroll
    for (int j = 0; j < 4; j++)
#pragma unroll
        for (int q = 0; q < 4; q++) o_[j][q] = 0.f;

    for (int kb = 0; kb < nkb; kb++) {
        cpa_wait0();
        __syncthreads();

        if (kb + 1 < nkb) {
            const int sn = (kb + 1) * 64;
            uint32_t* sKn = sK + ((kb + 1) & 1) * SK_BUF;
            uint32_t* sVn = sV + ((kb + 1) & 1) * SV_BUF;
#pragma unroll
            for (int u = 0; u < 4; u++) {
                int idx = tid + u * 256;
                int dd = idx >> 4, sg = idx & 15;
                cpa16(s2u(&sKn[dd * SK_STRIDE + sg * 4]), kp + (size_t)dd * TT + sn + sg * 4);
            }
#pragma unroll
            for (int u = 0; u < 2; u++) {
                int idx = tid + u * 256;
                int dd = idx >> 4, sg = idx & 15;
                cpa16(s2u(&sVn[dd * SV_STRIDE + sg * 4]), vp + (size_t)dd * TT + sn + sg * 4);
            }
            cpa_commit();
        }

        const int s0 = kb * 64;
        const bool active = (s0 <= t0w + 15);
        if (active) {
            const uint32_t* sKb = sK + (kb & 1) * SK_BUF;
            const uint32_t* sVb = sV + (kb & 1) * SV_BUF;

            float s[8][4];
#pragma unroll
            for (int j = 0; j < 8; j++)
#pragma unroll
                for (int q = 0; q < 4; q++) s[j][q] = 0.f;

#pragma unroll
            for (int kd = 0; kd < 8; kd++) {
                const int kc = kd * 8;
#pragma unroll
                for (int j = 0; j < 8; j++) {
                    uint32_t b0 = sKb[(kc + lc) * SK_STRIDE + j * 8 + lr];
                    uint32_t b1 = sKb[(kc + 4 + lc) * SK_STRIDE + j * 8 + lr];
                    mma8(s[j], qfr[kd], b0, b1);
                }
            }

            const int tg0 = t0w + lr, tg1 = tg0 + 8;
            const bool need_mask = (s0 + 63 > t0w);
#pragma unroll
            for (int j = 0; j < 8; j++) {
                int sg = s0 + j * 8 + lc * 2;
                s[j][0] *= scale; s[j][1] *= scale; s[j][2] *= scale; s[j][3] *= scale;
                if (need_mask) {
                    if (sg     > tg0) s[j][0] = -1e30f;
                    if (sg + 1 > tg0) s[j][1] = -1e30f;
                    if (sg     > tg1) s[j][2] = -1e30f;
                    if (sg + 1 > tg1) s[j][3] = -1e30f;
                }
            }

            float mn0 = -1e30f, mn1 = -1e30f;
#pragma unroll
            for (int j = 0; j < 8; j++) {
                mn0 = fmaxf(mn0, fmaxf(s[j][0], s[j][1]));
                mn1 = fmaxf(mn1, fmaxf(s[j][2], s[j][3]));
            }
            mn0 = fmaxf(mn0, __shfl_xor_sync(0xffffffffu, mn0, 1));
            mn0 = fmaxf(mn0, __shfl_xor_sync(0xffffffffu, mn0, 2));
            mn1 = fmaxf(mn1, __shfl_xor_sync(0xffffffffu, mn1, 1));
            mn1 = fmaxf(mn1, __shfl_xor_sync(0xffffffffu, mn1, 2));

            float mN0 = fmaxf(m0, mn0), mN1 = fmaxf(m1, mn1);
            float al0 = __expf(m0 - mN0), al1 = __expf(m1 - mN1);
            m0 = mN0; m1 = mN1;

            float rs0 = 0.f, rs1 = 0.f;
#pragma unroll
            for (int j = 0; j < 8; j++) {
                s[j][0] = __expf(s[j][0] - m0); rs0 += s[j][0];
                s[j][1] = __expf(s[j][1] - m0); rs0 += s[j][1];
                s[j][2] = __expf(s[j][2] - m1); rs1 += s[j][2];
                s[j][3] = __expf(s[j][3] - m1); rs1 += s[j][3];
            }
            rs0 += __shfl_xor_sync(0xffffffffu, rs0, 1);
            rs0 += __shfl_xor_sync(0xffffffffu, rs0, 2);
            rs1 += __shfl_xor_sync(0xffffffffu, rs1, 1);
            rs1 += __shfl_xor_sync(0xffffffffu, rs1, 2);
            l0 = l0 * al0 + rs0;
            l1 = l1 * al1 + rs1;

#pragma unroll
            for (int j = 0; j < 4; j++) {
                o_[j][0] *= al0; o_[j][1] *= al0;
                o_[j][2] *= al1; o_[j][3] *= al1;
            }

            {
                const int r0 = w * 16 + lr;
#pragma unroll
                for (int j = 0; j < 8; j++) {
                    int c = j * 8 + lc * 2;
                    sP[r0 * SP_STRIDE + c]           = f2tf(s[j][0]);
                    sP[r0 * SP_STRIDE + c + 1]       = f2tf(s[j][1]);
                    sP[(r0 + 8) * SP_STRIDE + c]     = f2tf(s[j][2]);
                    sP[(r0 + 8) * SP_STRIDE + c + 1] = f2tf(s[j][3]);
                }
            }
            __syncwarp();

            // sVb is [dv][s]: B element (k=s, n=dv) at sVb[dv*SV_STRIDE + s]
#pragma unroll
            for (int ksx = 0; ksx < 8; ksx++) {
                const int ks = ksx * 8;
                uint32_t a[4];
                a[0] = sP[(w * 16 + lr) * SP_STRIDE + ks + lc];
                a[1] = sP[(w * 16 + lr + 8) * SP_STRIDE + ks + lc];
                a[2] = sP[(w * 16 + lr) * SP_STRIDE + ks + 4 + lc];
                a[3] = sP[(w * 16 + lr + 8) * SP_STRIDE + ks + 4 + lc];
#pragma unroll
                for (int j = 0; j < 4; j++) {
                    uint32_t b0 = sVb[(j * 8 + lr) * SV_STRIDE + ks + lc];
                    uint32_t b1 = sVb[(j * 8 + lr) * SV_STRIDE + ks + 4 + lc];
                    mma8(o_[j], a, b0, b1);
                }
            }
        }
    }

    const int n = nh >> 3, h = nh & 7;
    float* __restrict__ aob = g_ao + ((size_t)n * OCH + h * DV) * TT;
    const float inv0 = 1.f / l0, inv1 = 1.f / l1;
    const int tg0 = t0w + lr, tg1 = tg0 + 8;
#pragma unroll
    for (int j = 0; j < 4; j++) {
        int dv = j * 8 + lc * 2;
        aob[(size_t)dv * TT + tg0]       = f2tf_f(o_[j][0] * inv0);
        aob[(size_t)(dv + 1) * TT + tg0] = f2tf_f(o_[j][1] * inv0);
        aob[(size_t)dv * TT + tg1]       = f2tf_f(o_[j][2] * inv1);
        aob[(size_t)(dv + 1) * TT + tg1] = f2tf_f(o_[j][3] * inv1);
    }
}

// ---------------------------------------------------------------------------
// Kernel 3: output projection, cp.async double-buffered (same as qkv).
// grid: (T/128, 256/128, NB)
// ---------------------------------------------------------------------------
__global__ __launch_bounds__(256, 2) void out_proj_kernel(
    const float* __restrict__ bo, float* __restrict__ out)
{
    extern __shared__ uint32_t gsm[];
    const int n  = blockIdx.z;
    const int o0 = blockIdx.y * 128;
    const int t0 = blockIdx.x * 128;
    const int tid = threadIdx.x;
    const int lane = tid & 31, wid = tid >> 5;
    const int wo = wid >> 1, wt = wid & 1;
    const int lr = lane >> 2, lc = lane & 3;

    const float* __restrict__ wsrc = g_wo + (size_t)o0 * OCH;
    const float* __restrict__ xsrc = g_ao + (size_t)n * OCH * TT + t0;

    float d[2][8][4];
#pragma unroll
    for (int mi = 0; mi < 2; mi++)
#pragma unroll
        for (int j = 0; j < 8; j++)
#pragma unroll
            for (int q = 0; q < 4; q++) d[mi][j][q] = 0.f;

    gemm_fill_stage(gsm, gsm + GA_BUF, wsrc, xsrc, 0, tid);

#pragma unroll
    for (int st = 0; st < 8; st++) {
        uint32_t* sA = gsm + (st & 1) * GSTAGE;
        uint32_t* sB = sA + GA_BUF;
        if (st + 1 < 8) {
            uint32_t* nA = gsm + ((st + 1) & 1) * GSTAGE;
            gemm_fill_stage(nA, nA + GA_BUF, wsrc, xsrc, (st + 1) * 32, tid);
            cpa_wait1();
        } else {
            cpa_wait0();
        }
        __syncthreads();

#pragma unroll
        for (int kk = 0; kk < 4; kk++) {
            const int kc = kk * 8;
            uint32_t a[2][4];
#pragma unroll
            for (int mi = 0; mi < 2; mi++) {
                int row = wo * 32 + mi * 16 + lr;
                a[mi][0] = sA[row * GA_W + kc + lc];
                a[mi][1] = sA[(row + 8) * GA_W + kc + lc];
                a[mi][2] = sA[row * GA_W + kc + 4 + lc];
                a[mi][3] = sA[(row + 8) * GA_W + kc + 4 + lc];
            }
#pragma unroll
            for (int j = 0; j < 8; j++) {
                int col = wt * 64 + j * 8 + lr;
                uint32_t b0 = sB[(kc + lc) * GB_W + col];
                uint32_t b1 = sB[(kc + 4 + lc) * GB_W + col];
                mma8(d[0][j], a[0], b0, b1);
                mma8(d[1][j], a[1], b0, b1);
            }
        }
        __syncthreads();
    }

#pragma unroll
    for (int mi = 0; mi < 2; mi++) {
#pragma unroll
        for (int half = 0; half < 2; half++) {
            int o = o0 + wo * 32 + mi * 16 + half * 8 + lr;
            float bias = bo[o];
            float* dst = out + ((size_t)n * OCH + o) * TT;
#pragma unroll
            for (int j = 0; j < 8; j++) {
                int t = t0 + wt * 64 + j * 8 + lc * 2;
                dst[t]     = d[mi][j][half * 2 + 0] + bias;
                dst[t + 1] = d[mi][j][half * 2 + 1] + bias;
            }
        }
    }
}

// ---------------------------------------------------------------------------
extern "C" void kernel_launch(void* const* d_in, const int* in_sizes, int n_in,
                              void* d_out, int out_size)
{
    const float* x   = (const float*)d_in[0];
    const float* Wq  = (const float*)d_in[1];
    const float* bq  = (const float*)d_in[2];
    const float* Wkv = (const float*)d_in[3];
    const float* bkv = (const float*)d_in[4];
    const float* Wo  = (const float*)d_in[5];
    const float* bo  = (const float*)d_in[6];
    float* out = (float*)d_out;

    cudaFuncSetAttribute(attn_kernel,
                         cudaFuncAttributeMaxDynamicSharedMemorySize,
                         ATTN_SMEM_WORDS * 4);
    cudaFuncSetAttribute(qkv_kernel,
                         cudaFuncAttributeMaxDynamicSharedMemorySize,
                         GEMM_SMEM_BYTES);
    cudaFuncSetAttribute(out_proj_kernel,
                         cudaFuncAttributeMaxDynamicSharedMemorySize,
                         GEMM_SMEM_BYTES);

    round_pre_kernel<<<1024, 256>>>(x, Wq, Wkv, Wo);
    qkv_kernel<<<dim3(TT / 128, 1280 / 128, NB), 256, GEMM_SMEM_BYTES>>>(bq, bkv);
    attn_kernel<<<dim3(TT / 128, NB * HDS), 256, ATTN_SMEM_WORDS * 4>>>();
    out_proj_kernel<<<dim3(TT / 128, OCH / 128, NB), 256, GEMM_SMEM_BYTES>>>(bo, out);
}